// round 1
// baseline (speedup 1.0000x reference)
#include <cuda_runtime.h>
#include <math.h>

// ---------------------------------------------------------------------------
// SwinTransformer block, B=128, FMAP=56, WS=7, SHIFT=3, NH=3, C=96, FF=384
// Strategy: keep everything in original (B,S,C) token layout; only attention
// gathers shifted-window token groups via index math (permutation commutes
// with all pointwise ops). Region mask computed on the fly.
// ---------------------------------------------------------------------------

#define T_TOK   401408        // 128 * 3136 tokens
#define CDIM    96
#define FFDIM   384
#define QKVDIM  288

// Scratch (static device globals: allowed; runtime allocs are not)
__device__ float g_h   [T_TOK * CDIM];    // LN1 out; reused as attention output o
__device__ float g_qkv [T_TOK * QKVDIM];  // qkv; reused as h2 (LN2 out)
__device__ float g_x1  [T_TOK * CDIM];    // x + attn residual
__device__ float g_ff  [T_TOK * FFDIM];   // gelu(ff1) activations

// ---------------------------------------------------------------------------
// LayerNorm: one warp per token (96 channels -> 3 per lane)
// ---------------------------------------------------------------------------
__global__ __launch_bounds__(128)
void ln_kernel(const float* __restrict__ x, const float* __restrict__ w,
               const float* __restrict__ b, float* __restrict__ h)
{
    int warp = threadIdx.x >> 5;
    int lane = threadIdx.x & 31;
    size_t t = (size_t)blockIdx.x * 4 + warp;
    const float* xr = x + t * CDIM;
    float v0 = xr[lane], v1 = xr[lane + 32], v2 = xr[lane + 64];
    float s = v0 + v1 + v2;
    #pragma unroll
    for (int o = 16; o; o >>= 1) s += __shfl_xor_sync(0xffffffffu, s, o);
    float mu = s * (1.0f / 96.0f);
    float d0 = v0 - mu, d1 = v1 - mu, d2 = v2 - mu;
    float vv = d0 * d0 + d1 * d1 + d2 * d2;
    #pragma unroll
    for (int o = 16; o; o >>= 1) vv += __shfl_xor_sync(0xffffffffu, vv, o);
    float inv = rsqrtf(vv * (1.0f / 96.0f) + 1e-5f);
    float* hr = h + t * CDIM;
    hr[lane]      = d0 * inv * w[lane]      + b[lane];
    hr[lane + 32] = d1 * inv * w[lane + 32] + b[lane + 32];
    hr[lane + 64] = d2 * inv * w[lane + 64] + b[lane + 64];
}

// ---------------------------------------------------------------------------
// GEMM: C[M,N] = A[M,K] @ W[N,K]^T + bias, optional epilogue.
// BM=64, BN=96, BK=32, 256 threads, 4x6 thread tile.
// EPI: 0 = bias, 1 = bias + residual (res stride N), 2 = bias + exact GELU
// ---------------------------------------------------------------------------
template<int N, int K, int EPI>
__global__ __launch_bounds__(256)
void gemm_kernel(const float* __restrict__ A, const float* __restrict__ W,
                 const float* __restrict__ bias, const float* __restrict__ res,
                 float* __restrict__ C)
{
    __shared__ float As[32][65];   // padded: avoid 32-way store conflicts
    __shared__ float Bs[32][97];

    int tid = threadIdx.x;
    int ty = tid >> 4;             // 0..15  (4 rows each)
    int tx = tid & 15;             // 0..15  (6 cols each)
    int row0 = blockIdx.y * 64;
    int col0 = blockIdx.x * 96;

    float acc[4][6];
    #pragma unroll
    for (int m = 0; m < 4; ++m)
        #pragma unroll
        for (int n = 0; n < 6; ++n) acc[m][n] = 0.0f;

    for (int kk = 0; kk < K; kk += 32) {
        #pragma unroll
        for (int i = tid; i < 64 * 32; i += 256) {
            int r = i >> 5, k = i & 31;
            As[k][r] = A[(size_t)(row0 + r) * K + kk + k];
        }
        #pragma unroll
        for (int i = tid; i < 96 * 32; i += 256) {
            int c = i >> 5, k = i & 31;
            Bs[k][c] = W[(size_t)(col0 + c) * K + kk + k];
        }
        __syncthreads();
        #pragma unroll
        for (int k = 0; k < 32; ++k) {
            float a[4], bv[6];
            #pragma unroll
            for (int m = 0; m < 4; ++m) a[m] = As[k][ty * 4 + m];
            #pragma unroll
            for (int n = 0; n < 6; ++n) bv[n] = Bs[k][tx * 6 + n];
            #pragma unroll
            for (int m = 0; m < 4; ++m)
                #pragma unroll
                for (int n = 0; n < 6; ++n) acc[m][n] += a[m] * bv[n];
        }
        __syncthreads();
    }

    #pragma unroll
    for (int m = 0; m < 4; ++m) {
        int row = row0 + ty * 4 + m;
        #pragma unroll
        for (int n = 0; n < 6; ++n) {
            int col = col0 + tx * 6 + n;
            float v = acc[m][n] + bias[col];
            if (EPI == 1) v += res[(size_t)row * N + col];
            if (EPI == 2) v = 0.5f * v * (1.0f + erff(v * 0.70710678118654752f));
            C[(size_t)row * N + col] = v;
        }
    }
}

// ---------------------------------------------------------------------------
// Windowed attention: one block per (window, head). 64 threads.
// qkv layout: [T, 288] = [q(96) | k(96) | v(96)], head h -> cols h*32..
// ---------------------------------------------------------------------------
__global__ __launch_bounds__(64)
void attn_kernel(const float* __restrict__ qkv, float* __restrict__ o)
{
    __shared__ float ks[49][32];
    __shared__ float vs[49][32];
    __shared__ float ss[49][49];   // scores per query row; stride 49 (odd) -> conflict-free
    __shared__ int   tokS[49];
    __shared__ int   regS[49];

    int bid  = blockIdx.x;
    int head = bid % 3;
    int win  = bid / 3;            // 0..8191
    int b    = win >> 6;           // batch
    int w    = win & 63;
    int wr   = w >> 3, wc = w & 7;
    int tid  = threadIdx.x;

    if (tid < 49) {
        int lr = tid / 7, lc = tid % 7;
        int ri = wr * 7 + lr, rj = wc * 7 + lc;       // rolled coords
        int oi = ri + 3; if (oi >= 56) oi -= 56;      // original coords
        int oj = rj + 3; if (oj >= 56) oj -= 56;
        tokS[tid] = b * 3136 + oi * 56 + oj;
        regS[tid] = 3 * ((ri >= 49) + (ri >= 53)) + ((rj >= 49) + (rj >= 53));
    }
    __syncthreads();

    int kbase = 96 + head * 32;
    int vbase = 192 + head * 32;
    for (int i = tid; i < 49 * 32; i += 64) {
        int j = i >> 5, d = i & 31;
        size_t t = (size_t)tokS[j] * QKVDIM;
        ks[j][d] = qkv[t + kbase + d];
        vs[j][d] = qkv[t + vbase + d];
    }
    __syncthreads();

    if (tid < 49) {
        size_t t = (size_t)tokS[tid] * QKVDIM;
        float q[32];
        #pragma unroll
        for (int d = 0; d < 32; ++d) q[d] = qkv[t + head * 32 + d];

        const float scale = 0.17677669529663688f;  // 1/sqrt(32)
        int myreg = regS[tid];
        float mx = -1e30f;
        for (int j = 0; j < 49; ++j) {
            float acc = 0.0f;
            #pragma unroll
            for (int d = 0; d < 32; ++d) acc += q[d] * ks[j][d];
            acc *= scale;
            if (regS[j] != myreg) acc -= 1e9f;
            ss[tid][j] = acc;
            mx = fmaxf(mx, acc);
        }
        float sum = 0.0f;
        for (int j = 0; j < 49; ++j) {
            float e = expf(ss[tid][j] - mx);
            ss[tid][j] = e;
            sum += e;
        }
        float inv = 1.0f / sum;
        float* orow = o + (size_t)tokS[tid] * CDIM + head * 32;
        #pragma unroll
        for (int d = 0; d < 32; ++d) {
            float acc = 0.0f;
            for (int j = 0; j < 49; ++j) acc += ss[tid][j] * vs[j][d];
            orow[d] = acc * inv;
        }
    }
}

// ---------------------------------------------------------------------------
// Launch
// ---------------------------------------------------------------------------
extern "C" void kernel_launch(void* const* d_in, const int* in_sizes, int n_in,
                              void* d_out, int out_size)
{
    const float* x     = (const float*)d_in[0];
    const float* qkv_w = (const float*)d_in[1];
    const float* qkv_b = (const float*)d_in[2];
    const float* out_w = (const float*)d_in[3];
    const float* out_b = (const float*)d_in[4];
    const float* ln1_w = (const float*)d_in[5];
    const float* ln1_b = (const float*)d_in[6];
    const float* ln2_w = (const float*)d_in[7];
    const float* ln2_b = (const float*)d_in[8];
    const float* ff1_w = (const float*)d_in[9];
    const float* ff1_b = (const float*)d_in[10];
    const float* ff2_w = (const float*)d_in[11];
    const float* ff2_b = (const float*)d_in[12];
    float* out = (float*)d_out;

    float *p_h, *p_qkv, *p_x1, *p_ff;
    cudaGetSymbolAddress((void**)&p_h,   g_h);
    cudaGetSymbolAddress((void**)&p_qkv, g_qkv);
    cudaGetSymbolAddress((void**)&p_x1,  g_x1);
    cudaGetSymbolAddress((void**)&p_ff,  g_ff);

    const int MB = T_TOK / 64;    // 6272 row-blocks

    // 1. h = LN1(x)
    ln_kernel<<<T_TOK / 4, 128>>>(x, ln1_w, ln1_b, p_h);
    // 2. qkv = h @ qkv_w^T + qkv_b
    gemm_kernel<QKVDIM, CDIM, 0><<<dim3(3, MB), 256>>>(p_h, qkv_w, qkv_b, nullptr, p_qkv);
    // 3. o = windowed masked attention (writes into g_h, reuse)
    attn_kernel<<<8192 * 3, 64>>>(p_qkv, p_h);
    // 4. x1 = x + o @ out_w^T + out_b
    gemm_kernel<CDIM, CDIM, 1><<<dim3(1, MB), 256>>>(p_h, out_w, out_b, x, p_x1);
    // 5. h2 = LN2(x1) (into g_qkv, reuse)
    ln_kernel<<<T_TOK / 4, 128>>>(p_x1, ln2_w, ln2_b, p_qkv);
    // 6. ff = gelu(h2 @ ff1_w^T + ff1_b)
    gemm_kernel<FFDIM, CDIM, 2><<<dim3(4, MB), 256>>>(p_qkv, ff1_w, ff1_b, nullptr, p_ff);
    // 7. out = x1 + ff @ ff2_w^T + ff2_b
    gemm_kernel<CDIM, FFDIM, 1><<<dim3(1, MB), 256>>>(p_ff, ff2_w, ff2_b, p_x1, out);
}

// round 3
// speedup vs baseline: 2.1850x; 2.1850x over previous
#include <cuda_runtime.h>
#include <cuda_bf16.h>
#include <math.h>
#include <stdint.h>

// ---------------------------------------------------------------------------
// SwinTransformer block, B=128, FMAP=56, WS=7, SHIFT=3, NH=3, C=96, FF=384
// Round 3: warp-level HMMA (mma.sync m16n8k16 bf16) GEMMs — tcgen05 is
// arch-'a'-gated and this toolchain emits compute_103 PTX. bf16 intermediates,
// fused epilogues, index-math shifted-window attention.
// ---------------------------------------------------------------------------

#define T_TOK 401408

// Scratch (static device globals)
__device__ __nv_bfloat16 g_h  [(size_t)T_TOK * 128];  // LN1 out (pad 128); reused as attn o
__device__ __nv_bfloat16 g_qkv[(size_t)T_TOK * 288];  // qkv; reused as h2 (LN2 out [T,128])
__device__ float         g_x1 [(size_t)T_TOK * 96];   // x + attn residual (fp32 trunk)
__device__ __nv_bfloat16 g_ff [(size_t)T_TOK * 384];  // gelu(ff1)

__device__ __forceinline__ uint32_t smem_u32(const void* p) {
    uint32_t a;
    asm("{ .reg .u64 t; cvta.to.shared.u64 t, %1; cvt.u32.u64 %0, t; }" : "=r"(a) : "l"(p));
    return a;
}

__device__ __forceinline__ uint32_t f2bf2(float lo, float hi) {
    __nv_bfloat162 h2 = __floats2bfloat162_rn(lo, hi);
    return *reinterpret_cast<uint32_t*>(&h2);
}

__device__ __forceinline__ void ldmx4(uint32_t* r, uint32_t addr) {
    asm volatile("ldmatrix.sync.aligned.m8n8.x4.shared.b16 {%0,%1,%2,%3}, [%4];"
                 : "=r"(r[0]), "=r"(r[1]), "=r"(r[2]), "=r"(r[3]) : "r"(addr));
}

__device__ __forceinline__ void mma_bf16(float* c, const uint32_t* a, uint32_t b0, uint32_t b1) {
    asm volatile(
        "mma.sync.aligned.m16n8k16.row.col.f32.bf16.bf16.f32 "
        "{%0,%1,%2,%3}, {%4,%5,%6,%7}, {%8,%9}, {%0,%1,%2,%3};"
        : "+f"(c[0]), "+f"(c[1]), "+f"(c[2]), "+f"(c[3])
        : "r"(a[0]), "r"(a[1]), "r"(a[2]), "r"(a[3]), "r"(b0), "r"(b1));
}

// ---------------------------------------------------------------------------
// LayerNorm: one warp per token, fp32 in, bf16 out padded to 128 cols
// ---------------------------------------------------------------------------
__global__ __launch_bounds__(128)
void ln_kernel(const float* __restrict__ x, const float* __restrict__ w,
               const float* __restrict__ b, __nv_bfloat16* __restrict__ h)
{
    int warp = threadIdx.x >> 5;
    int lane = threadIdx.x & 31;
    size_t t = (size_t)blockIdx.x * 4 + warp;
    const float* xr = x + t * 96;
    float v0 = xr[lane], v1 = xr[lane + 32], v2 = xr[lane + 64];
    float s = v0 + v1 + v2;
    #pragma unroll
    for (int o = 16; o; o >>= 1) s += __shfl_xor_sync(0xffffffffu, s, o);
    float mu = s * (1.0f / 96.0f);
    float d0 = v0 - mu, d1 = v1 - mu, d2 = v2 - mu;
    float vv = d0 * d0 + d1 * d1 + d2 * d2;
    #pragma unroll
    for (int o = 16; o; o >>= 1) vv += __shfl_xor_sync(0xffffffffu, vv, o);
    float inv = rsqrtf(vv * (1.0f / 96.0f) + 1e-5f);
    __nv_bfloat16* hr = h + t * 128;
    hr[lane]      = __float2bfloat16(d0 * inv * w[lane]      + b[lane]);
    hr[lane + 32] = __float2bfloat16(d1 * inv * w[lane + 32] + b[lane + 32]);
    hr[lane + 64] = __float2bfloat16(d2 * inv * w[lane + 64] + b[lane + 64]);
    hr[lane + 96] = __float2bfloat16(0.0f);   // K padding
}

// ---------------------------------------------------------------------------
// HMMA GEMM: tile C[128, 96] = A[128, NC*64] @ W[col0+96, KR]^T (+epilogue)
//   A bf16 gmem, row stride NC*64, zero-padded past KR.
//   W fp32 gmem [*, KR] -> bf16 in the tile loader (zero pad past KR).
//   Block 256 thr = 8 warps (4M x 2N), warp tile 32x48 (2x6 m16n8k16 frags).
//   EPI 0: +bias -> bf16 out stride NBT
//   EPI 1: +bias +res (fp32 [T,96]) -> fp32 out stride 96
//   EPI 2: +bias, exact GELU -> bf16 out stride NBT
// ---------------------------------------------------------------------------
template<int NBT, int KR, int NC, int EPI>
__global__ __launch_bounds__(256)
void gemm_hmma(const __nv_bfloat16* __restrict__ A, const float* __restrict__ W,
               const float* __restrict__ bias, const float* __restrict__ res,
               void* __restrict__ out)
{
    __shared__ __nv_bfloat16 As[128][72];   // 144B row stride -> conflict-free ldmatrix
    __shared__ __nv_bfloat16 Bs[96][72];

    int tid  = threadIdx.x;
    int wid  = tid >> 5;
    int lane = tid & 31;
    int mw = wid >> 1;                 // 0..3
    int nw = wid & 1;                  // 0..1
    size_t row0 = (size_t)blockIdx.y * 128;
    int col0 = blockIdx.x * 96;

    uint32_t sAs = smem_u32(&As[0][0]);
    uint32_t sBs = smem_u32(&Bs[0][0]);

    float c[2][6][4];
    #pragma unroll
    for (int fm = 0; fm < 2; ++fm)
        #pragma unroll
        for (int fn = 0; fn < 6; ++fn)
            #pragma unroll
            for (int r = 0; r < 4; ++r) c[fm][fn][r] = 0.0f;

    for (int ch = 0; ch < NC; ++ch) {
        // load A chunk: 128 rows x 64 bf16 (16B vectors)
        #pragma unroll
        for (int u = tid; u < 1024; u += 256) {
            int r = u >> 3, sgm = u & 7;
            uint4 v = *(const uint4*)(A + (row0 + r) * (NC * 64) + ch * 64 + sgm * 8);
            *(uint4*)(&As[r][sgm * 8]) = v;
        }
        // load B chunk: 96 rows x 64, fp32 -> bf16, zero-pad past KR
        #pragma unroll
        for (int u = tid; u < 768; u += 256) {
            int n = u >> 3, sgm = u & 7;
            int k0 = ch * 64 + sgm * 8;
            uint4 v;
            if (k0 < KR) {
                const float4* wp = (const float4*)(W + (size_t)(col0 + n) * KR + k0);
                float4 f0 = wp[0], f1 = wp[1];
                v.x = f2bf2(f0.x, f0.y); v.y = f2bf2(f0.z, f0.w);
                v.z = f2bf2(f1.x, f1.y); v.w = f2bf2(f1.z, f1.w);
            } else {
                v.x = v.y = v.z = v.w = 0u;
            }
            *(uint4*)(&Bs[n][sgm * 8]) = v;
        }
        __syncthreads();

        int lrow = lane & 15;          // ldmatrix row within 16
        int lk8  = (lane >> 4) * 8;    // k-half select
        #pragma unroll
        for (int ks = 0; ks < 4; ++ks) {
            int k0 = ks * 16;
            uint32_t a[2][4];
            #pragma unroll
            for (int fm = 0; fm < 2; ++fm)
                ldmx4(a[fm], sAs + ((mw * 32 + fm * 16 + lrow) * 72 + k0 + lk8) * 2);
            uint32_t bfr[3][4];
            #pragma unroll
            for (int f3 = 0; f3 < 3; ++f3)
                ldmx4(bfr[f3], sBs + ((nw * 48 + f3 * 16 + lrow) * 72 + k0 + lk8) * 2);
            #pragma unroll
            for (int fm = 0; fm < 2; ++fm)
                #pragma unroll
                for (int fn = 0; fn < 6; ++fn) {
                    int f3 = fn >> 1, od = fn & 1;
                    mma_bf16(c[fm][fn], a[fm], bfr[f3][od], bfr[f3][od + 2]);
                }
        }
        __syncthreads();
    }

    // epilogue: register frags -> gmem, fused bias/res/gelu
    #pragma unroll
    for (int fm = 0; fm < 2; ++fm) {
        #pragma unroll
        for (int fn = 0; fn < 6; ++fn) {
            int colg = col0 + nw * 48 + fn * 8 + (lane & 3) * 2;
            float b0 = bias[colg], b1 = bias[colg + 1];
            #pragma unroll
            for (int hh = 0; hh < 2; ++hh) {   // hh=0 -> regs 0,1 ; hh=1 -> regs 2,3
                size_t rowg = row0 + mw * 32 + fm * 16 + (lane >> 2) + hh * 8;
                float v0 = c[fm][fn][hh * 2]     + b0;
                float v1 = c[fm][fn][hh * 2 + 1] + b1;
                if (EPI == 1) {
                    const float2 rr = *(const float2*)(res + rowg * 96 + colg);
                    v0 += rr.x; v1 += rr.y;
                    *(float2*)((float*)out + rowg * 96 + colg) = make_float2(v0, v1);
                } else if (EPI == 2) {
                    v0 = 0.5f * v0 * (1.0f + erff(v0 * 0.70710678118654752f));
                    v1 = 0.5f * v1 * (1.0f + erff(v1 * 0.70710678118654752f));
                    *(uint32_t*)((__nv_bfloat16*)out + rowg * NBT + colg) = f2bf2(v0, v1);
                } else {
                    *(uint32_t*)((__nv_bfloat16*)out + rowg * NBT + colg) = f2bf2(v0, v1);
                }
            }
        }
    }
}

// ---------------------------------------------------------------------------
// Windowed attention: one block per (window, head). 64 threads.
// qkv bf16 [T,288]; o bf16 [T,128] (head-0 blocks zero cols 96..127).
// ---------------------------------------------------------------------------
__global__ __launch_bounds__(64)
void attn_kernel(const __nv_bfloat16* __restrict__ qkv, __nv_bfloat16* __restrict__ o)
{
    __shared__ float ks[49][32];
    __shared__ float vs[49][32];
    __shared__ int   tokS[49];
    __shared__ int   regS[49];

    int bid  = blockIdx.x;
    int head = bid % 3;
    int win  = bid / 3;
    int b    = win >> 6;
    int w    = win & 63;
    int wr   = w >> 3, wc = w & 7;
    int tid  = threadIdx.x;

    if (tid < 49) {
        int lr = tid / 7, lc = tid % 7;
        int ri = wr * 7 + lr, rj = wc * 7 + lc;
        int oi = ri + 3; if (oi >= 56) oi -= 56;
        int oj = rj + 3; if (oj >= 56) oj -= 56;
        tokS[tid] = b * 3136 + oi * 56 + oj;
        regS[tid] = 3 * ((ri >= 49) + (ri >= 53)) + ((rj >= 49) + (rj >= 53));
    }
    __syncthreads();

    int kbase = 96 + head * 32;
    int vbase = 192 + head * 32;
    for (int i = tid; i < 49 * 32; i += 64) {
        int j = i >> 5, d = i & 31;
        size_t t = (size_t)tokS[j] * 288;
        ks[j][d] = __bfloat162float(qkv[t + kbase + d]);
        vs[j][d] = __bfloat162float(qkv[t + vbase + d]);
    }
    __syncthreads();

    if (tid < 49) {
        size_t t = (size_t)tokS[tid] * 288;
        float q[32];
        #pragma unroll
        for (int d = 0; d < 32; ++d)
            q[d] = __bfloat162float(qkv[t + head * 32 + d]);

        const float scale = 0.17677669529663688f;  // 1/sqrt(32)
        int myreg = regS[tid];
        float s[49];
        float mx = -1e30f;
        for (int j = 0; j < 49; ++j) {
            float acc = 0.0f;
            #pragma unroll
            for (int d = 0; d < 32; ++d) acc += q[d] * ks[j][d];
            acc *= scale;
            if (regS[j] != myreg) acc -= 1e9f;
            s[j] = acc;
            mx = fmaxf(mx, acc);
        }
        float sum = 0.0f;
        for (int j = 0; j < 49; ++j) {
            float e = __expf(s[j] - mx);
            s[j] = e;
            sum += e;
        }
        float inv = 1.0f / sum;
        __nv_bfloat16* orow = o + (size_t)tokS[tid] * 128 + head * 32;
        #pragma unroll
        for (int d = 0; d < 32; ++d) {
            float acc = 0.0f;
            for (int j = 0; j < 49; ++j) acc += s[j] * vs[j][d];
            orow[d] = __float2bfloat16(acc * inv);
        }
        if (head == 0) {
            __nv_bfloat16* prow = o + (size_t)tokS[tid] * 128 + 96;
            #pragma unroll
            for (int d = 0; d < 32; ++d) prow[d] = __float2bfloat16(0.0f);
        }
    }
}

// ---------------------------------------------------------------------------
// Launch
// ---------------------------------------------------------------------------
extern "C" void kernel_launch(void* const* d_in, const int* in_sizes, int n_in,
                              void* d_out, int out_size)
{
    const float* x     = (const float*)d_in[0];
    const float* qkv_w = (const float*)d_in[1];
    const float* qkv_b = (const float*)d_in[2];
    const float* out_w = (const float*)d_in[3];
    const float* out_b = (const float*)d_in[4];
    const float* ln1_w = (const float*)d_in[5];
    const float* ln1_b = (const float*)d_in[6];
    const float* ln2_w = (const float*)d_in[7];
    const float* ln2_b = (const float*)d_in[8];
    const float* ff1_w = (const float*)d_in[9];
    const float* ff1_b = (const float*)d_in[10];
    const float* ff2_w = (const float*)d_in[11];
    const float* ff2_b = (const float*)d_in[12];
    float* out = (float*)d_out;

    __nv_bfloat16 *p_h, *p_qkv, *p_ff;
    float *p_x1;
    cudaGetSymbolAddress((void**)&p_h,   g_h);
    cudaGetSymbolAddress((void**)&p_qkv, g_qkv);
    cudaGetSymbolAddress((void**)&p_x1,  g_x1);
    cudaGetSymbolAddress((void**)&p_ff,  g_ff);

    const int MB = T_TOK / 128;   // 3136 row tiles

    // 1. h = LN1(x)                                   (bf16 [T,128])
    ln_kernel<<<T_TOK / 4, 128>>>(x, ln1_w, ln1_b, p_h);
    // 2. qkv = h @ qkv_w^T + qkv_b                    (bf16 [T,288])
    gemm_hmma<288, 96, 2, 0><<<dim3(3, MB), 256>>>(p_h, qkv_w, qkv_b, nullptr, p_qkv);
    // 3. o = windowed masked attention                (bf16 [T,128], into g_h)
    attn_kernel<<<8192 * 3, 64>>>(p_qkv, p_h);
    // 4. x1 = x + o @ out_w^T + out_b                 (fp32 [T,96])
    gemm_hmma<96, 96, 2, 1><<<dim3(1, MB), 256>>>(p_h, out_w, out_b, x, p_x1);
    // 5. h2 = LN2(x1)                                 (bf16 [T,128], into g_qkv)
    ln_kernel<<<T_TOK / 4, 128>>>(p_x1, ln2_w, ln2_b, p_qkv);
    // 6. ff = gelu(h2 @ ff1_w^T + ff1_b)              (bf16 [T,384])
    gemm_hmma<384, 96, 2, 2><<<dim3(4, MB), 256>>>(p_qkv, ff1_w, ff1_b, nullptr, p_ff);
    // 7. out = x1 + ff @ ff2_w^T + ff2_b              (fp32 [T,96])
    gemm_hmma<96, 384, 6, 1><<<dim3(1, MB), 256>>>(p_ff, ff2_w, ff2_b, p_x1, out);
}

// round 4
// speedup vs baseline: 3.8431x; 1.7589x over previous
#include <cuda_runtime.h>
#include <cuda_bf16.h>
#include <math.h>
#include <stdint.h>

// ---------------------------------------------------------------------------
// SwinTransformer block, B=128, FMAP=56, WS=7, SHIFT=3, NH=3, C=96, FF=384
// Round 4: HMMA GEMMs + tensor-core windowed attention (mma m16n8k16),
// LN2 fused into the attention-proj GEMM epilogue.
// ---------------------------------------------------------------------------

#define T_TOK 401408

__device__ __nv_bfloat16 g_h  [(size_t)T_TOK * 128];  // LN1 out; reused as attn o
__device__ __nv_bfloat16 g_qkv[(size_t)T_TOK * 288];  // qkv; reused as h2 [T,128]
__device__ float         g_x1 [(size_t)T_TOK * 96];   // x + attn residual (fp32 trunk)
__device__ __nv_bfloat16 g_ff [(size_t)T_TOK * 384];  // gelu(ff1)

__device__ __forceinline__ uint32_t smem_u32(const void* p) {
    uint32_t a;
    asm("{ .reg .u64 t; cvta.to.shared.u64 t, %1; cvt.u32.u64 %0, t; }" : "=r"(a) : "l"(p));
    return a;
}
__device__ __forceinline__ uint32_t f2bf2(float lo, float hi) {
    __nv_bfloat162 h2 = __floats2bfloat162_rn(lo, hi);
    return *reinterpret_cast<uint32_t*>(&h2);
}
__device__ __forceinline__ void ldmx4(uint32_t* r, uint32_t addr) {
    asm volatile("ldmatrix.sync.aligned.m8n8.x4.shared.b16 {%0,%1,%2,%3}, [%4];"
                 : "=r"(r[0]), "=r"(r[1]), "=r"(r[2]), "=r"(r[3]) : "r"(addr));
}
__device__ __forceinline__ void ldmx4t(uint32_t* r, uint32_t addr) {
    asm volatile("ldmatrix.sync.aligned.m8n8.x4.trans.shared.b16 {%0,%1,%2,%3}, [%4];"
                 : "=r"(r[0]), "=r"(r[1]), "=r"(r[2]), "=r"(r[3]) : "r"(addr));
}
__device__ __forceinline__ void mma_bf16(float* c, const uint32_t* a, uint32_t b0, uint32_t b1) {
    asm volatile(
        "mma.sync.aligned.m16n8k16.row.col.f32.bf16.bf16.f32 "
        "{%0,%1,%2,%3}, {%4,%5,%6,%7}, {%8,%9}, {%0,%1,%2,%3};"
        : "+f"(c[0]), "+f"(c[1]), "+f"(c[2]), "+f"(c[3])
        : "r"(a[0]), "r"(a[1]), "r"(a[2]), "r"(a[3]), "r"(b0), "r"(b1));
}

// ---------------------------------------------------------------------------
// LayerNorm: one warp per token, fp32 in, bf16 out padded to 128 cols
// ---------------------------------------------------------------------------
__global__ __launch_bounds__(128)
void ln_kernel(const float* __restrict__ x, const float* __restrict__ w,
               const float* __restrict__ b, __nv_bfloat16* __restrict__ h)
{
    int warp = threadIdx.x >> 5;
    int lane = threadIdx.x & 31;
    size_t t = (size_t)blockIdx.x * 4 + warp;
    const float* xr = x + t * 96;
    float v0 = xr[lane], v1 = xr[lane + 32], v2 = xr[lane + 64];
    float s = v0 + v1 + v2;
    #pragma unroll
    for (int o = 16; o; o >>= 1) s += __shfl_xor_sync(0xffffffffu, s, o);
    float mu = s * (1.0f / 96.0f);
    float d0 = v0 - mu, d1 = v1 - mu, d2 = v2 - mu;
    float vv = d0 * d0 + d1 * d1 + d2 * d2;
    #pragma unroll
    for (int o = 16; o; o >>= 1) vv += __shfl_xor_sync(0xffffffffu, vv, o);
    float inv = rsqrtf(vv * (1.0f / 96.0f) + 1e-5f);
    __nv_bfloat16* hr = h + t * 128;
    hr[lane]      = __float2bfloat16(d0 * inv * w[lane]      + b[lane]);
    hr[lane + 32] = __float2bfloat16(d1 * inv * w[lane + 32] + b[lane + 32]);
    hr[lane + 64] = __float2bfloat16(d2 * inv * w[lane + 64] + b[lane + 64]);
    hr[lane + 96] = __float2bfloat16(0.0f);
}

// ---------------------------------------------------------------------------
// HMMA GEMM, tile C[128,96]. EPI 0: +bias->bf16 | 1: +bias+res->fp32
//   | 2: +bias,GELU->bf16 | 3: +bias+res->fp32 out AND fused LN -> h2 bf16.
// ---------------------------------------------------------------------------
template<int NBT, int KR, int NC, int EPI>
__global__ __launch_bounds__(256)
void gemm_hmma(const __nv_bfloat16* __restrict__ A, const float* __restrict__ W,
               const float* __restrict__ bias, const float* __restrict__ res,
               void* __restrict__ out,
               const float* __restrict__ lnw, const float* __restrict__ lnb,
               __nv_bfloat16* __restrict__ h2)
{
    __shared__ __align__(16) __nv_bfloat16 sbuf[128 * 72 + 96 * 72];
    auto As = (__nv_bfloat16 (*)[72])sbuf;
    auto Bs = (__nv_bfloat16 (*)[72])(sbuf + 128 * 72);

    int tid  = threadIdx.x;
    int wid  = tid >> 5;
    int lane = tid & 31;
    int mw = wid >> 1;
    int nw = wid & 1;
    size_t row0 = (size_t)blockIdx.y * 128;
    int col0 = blockIdx.x * 96;

    uint32_t sAs = smem_u32(&As[0][0]);
    uint32_t sBs = smem_u32(&Bs[0][0]);

    float c[2][6][4];
    #pragma unroll
    for (int fm = 0; fm < 2; ++fm)
        #pragma unroll
        for (int fn = 0; fn < 6; ++fn)
            #pragma unroll
            for (int r = 0; r < 4; ++r) c[fm][fn][r] = 0.0f;

    for (int ch = 0; ch < NC; ++ch) {
        #pragma unroll
        for (int u = tid; u < 1024; u += 256) {
            int r = u >> 3, sgm = u & 7;
            uint4 v = *(const uint4*)(A + (row0 + r) * (NC * 64) + ch * 64 + sgm * 8);
            *(uint4*)(&As[r][sgm * 8]) = v;
        }
        #pragma unroll
        for (int u = tid; u < 768; u += 256) {
            int n = u >> 3, sgm = u & 7;
            int k0 = ch * 64 + sgm * 8;
            uint4 v;
            if (k0 < KR) {
                const float4* wp = (const float4*)(W + (size_t)(col0 + n) * KR + k0);
                float4 f0 = wp[0], f1 = wp[1];
                v.x = f2bf2(f0.x, f0.y); v.y = f2bf2(f0.z, f0.w);
                v.z = f2bf2(f1.x, f1.y); v.w = f2bf2(f1.z, f1.w);
            } else {
                v.x = v.y = v.z = v.w = 0u;
            }
            *(uint4*)(&Bs[n][sgm * 8]) = v;
        }
        __syncthreads();

        int lrow = lane & 15;
        int lk8  = (lane >> 4) * 8;
        #pragma unroll
        for (int ks = 0; ks < 4; ++ks) {
            int k0 = ks * 16;
            uint32_t a[2][4];
            #pragma unroll
            for (int fm = 0; fm < 2; ++fm)
                ldmx4(a[fm], sAs + ((mw * 32 + fm * 16 + lrow) * 72 + k0 + lk8) * 2);
            uint32_t bfr[3][4];
            #pragma unroll
            for (int f3 = 0; f3 < 3; ++f3)
                ldmx4(bfr[f3], sBs + ((nw * 48 + f3 * 16 + lrow) * 72 + k0 + lk8) * 2);
            #pragma unroll
            for (int fm = 0; fm < 2; ++fm)
                #pragma unroll
                for (int fn = 0; fn < 6; ++fn) {
                    int f3 = fn >> 1, od = fn & 1;
                    mma_bf16(c[fm][fn], a[fm], bfr[f3][od], bfr[f3][od + 2]);
                }
        }
        __syncthreads();
    }

    __nv_bfloat16* stg = sbuf;   // EPI 3 stage: 128 x 104 bf16 (fits in sbuf)

    #pragma unroll
    for (int fm = 0; fm < 2; ++fm) {
        #pragma unroll
        for (int fn = 0; fn < 6; ++fn) {
            int colg = col0 + nw * 48 + fn * 8 + (lane & 3) * 2;
            float b0 = bias[colg], b1 = bias[colg + 1];
            #pragma unroll
            for (int hh = 0; hh < 2; ++hh) {
                int rloc = mw * 32 + fm * 16 + (lane >> 2) + hh * 8;
                size_t rowg = row0 + rloc;
                float v0 = c[fm][fn][hh * 2]     + b0;
                float v1 = c[fm][fn][hh * 2 + 1] + b1;
                if (EPI == 1 || EPI == 3) {
                    const float2 rr = *(const float2*)(res + rowg * 96 + colg);
                    v0 += rr.x; v1 += rr.y;
                    *(float2*)((float*)out + rowg * 96 + colg) = make_float2(v0, v1);
                    if (EPI == 3)
                        *(uint32_t*)(stg + rloc * 104 + colg) = f2bf2(v0, v1);
                } else if (EPI == 2) {
                    v0 = 0.5f * v0 * (1.0f + erff(v0 * 0.70710678118654752f));
                    v1 = 0.5f * v1 * (1.0f + erff(v1 * 0.70710678118654752f));
                    *(uint32_t*)((__nv_bfloat16*)out + rowg * NBT + colg) = f2bf2(v0, v1);
                } else {
                    *(uint32_t*)((__nv_bfloat16*)out + rowg * NBT + colg) = f2bf2(v0, v1);
                }
            }
        }
    }

    if (EPI == 3) {
        __syncthreads();
        for (int r = wid; r < 128; r += 8) {
            float v0 = __bfloat162float(stg[r * 104 + lane]);
            float v1 = __bfloat162float(stg[r * 104 + lane + 32]);
            float v2 = __bfloat162float(stg[r * 104 + lane + 64]);
            float s = v0 + v1 + v2;
            #pragma unroll
            for (int o = 16; o; o >>= 1) s += __shfl_xor_sync(0xffffffffu, s, o);
            float mu = s * (1.0f / 96.0f);
            float d0 = v0 - mu, d1 = v1 - mu, d2 = v2 - mu;
            float vv = d0 * d0 + d1 * d1 + d2 * d2;
            #pragma unroll
            for (int o = 16; o; o >>= 1) vv += __shfl_xor_sync(0xffffffffu, vv, o);
            float inv = rsqrtf(vv * (1.0f / 96.0f) + 1e-5f);
            __nv_bfloat16* hr = h2 + (row0 + r) * 128;
            hr[lane]      = __float2bfloat16(d0 * inv * lnw[lane]      + lnb[lane]);
            hr[lane + 32] = __float2bfloat16(d1 * inv * lnw[lane + 32] + lnb[lane + 32]);
            hr[lane + 64] = __float2bfloat16(d2 * inv * lnw[lane + 64] + lnb[lane + 64]);
            hr[lane + 96] = __float2bfloat16(0.0f);
        }
    }
}

// ---------------------------------------------------------------------------
// Tensor-core windowed attention: one block per window, 384 thr = 12 warps
// (3 heads x 4 M-tiles of 16 query rows). qkv bf16 [T,288] -> o bf16 [T,128].
// ---------------------------------------------------------------------------
__global__ __launch_bounds__(384)
void attn_mma(const __nv_bfloat16* __restrict__ qkv, __nv_bfloat16* __restrict__ o)
{
    __shared__ __nv_bfloat16 Qs[64][104];
    __shared__ __nv_bfloat16 Ks[64][104];
    __shared__ __nv_bfloat16 Vs[64][104];
    __shared__ int tokS[64];
    __shared__ int regS[64];

    int win = blockIdx.x;
    int b = win >> 6, w = win & 63;
    int wr = w >> 3, wc = w & 7;
    int tid = threadIdx.x, lane = tid & 31, wid = tid >> 5;

    if (tid < 64) {
        if (tid < 49) {
            int lr = tid / 7, lc = tid - lr * 7;
            int ri = wr * 7 + lr, rj = wc * 7 + lc;
            int oi = ri + 3; if (oi >= 56) oi -= 56;
            int oj = rj + 3; if (oj >= 56) oj -= 56;
            tokS[tid] = b * 3136 + oi * 56 + oj;
            regS[tid] = 3 * ((ri >= 49) + (ri >= 53)) + ((rj >= 49) + (rj >= 53));
        } else { tokS[tid] = 0; regS[tid] = -1; }
    }
    __syncthreads();

    // stage q,k,v (49 real rows x 96 cols; rows 49..63 zero)
    for (int u = tid; u < 64 * 12 * 3; u += 384) {
        int tsel = u / 768;
        int rem = u - tsel * 768;
        int r = rem / 12, cg = rem % 12;
        uint4 v = make_uint4(0u, 0u, 0u, 0u);
        if (r < 49)
            v = *(const uint4*)(qkv + (size_t)tokS[r] * 288 + tsel * 96 + cg * 8);
        __nv_bfloat16* dst = (tsel == 0) ? &Qs[0][0] : (tsel == 1) ? &Ks[0][0] : &Vs[0][0];
        *(uint4*)(dst + r * 104 + cg * 8) = v;
    }
    __syncthreads();

    int head = wid >> 2;          // 0..2
    int mt   = wid & 3;           // 0..3
    int lrow = lane & 15;
    int lk8  = (lane >> 4) << 3;
    uint32_t sQ = smem_u32(&Qs[0][0]);
    uint32_t sK = smem_u32(&Ks[0][0]);
    uint32_t sV = smem_u32(&Vs[0][0]);

    // ---- S = Q K^T : 8 n-frags of 8 cols ----
    float s[8][4];
    #pragma unroll
    for (int nt = 0; nt < 8; ++nt)
        #pragma unroll
        for (int r = 0; r < 4; ++r) s[nt][r] = 0.0f;

    #pragma unroll
    for (int kt = 0; kt < 2; ++kt) {
        uint32_t a[4];
        ldmx4(a, sQ + ((mt * 16 + lrow) * 104 + head * 32 + kt * 16 + lk8) * 2);
        #pragma unroll
        for (int nt16 = 0; nt16 < 4; ++nt16) {
            uint32_t bq[4];
            ldmx4(bq, sK + ((nt16 * 16 + lrow) * 104 + head * 32 + kt * 16 + lk8) * 2);
            mma_bf16(s[2 * nt16],     a, bq[0], bq[2]);
            mma_bf16(s[2 * nt16 + 1], a, bq[1], bq[3]);
        }
    }

    // ---- scale + mask + softmax (in C-fragment registers) ----
    int r_lo = mt * 16 + (lane >> 2);
    int r_hi = r_lo + 8;
    int mreg_lo = regS[r_lo];
    int mreg_hi = regS[r_hi];
    int c0 = (lane & 3) * 2;
    const float scale = 0.17677669529663688f;

    float mx_lo = -1e30f, mx_hi = -1e30f;
    #pragma unroll
    for (int nt = 0; nt < 8; ++nt) {
        int j0 = nt * 8 + c0, j1 = j0 + 1;
        int rg0 = regS[j0], rg1 = regS[j1];
        float v0 = s[nt][0] * scale + ((rg0 != mreg_lo) ? -1e9f : 0.0f);
        float v1 = s[nt][1] * scale + ((rg1 != mreg_lo) ? -1e9f : 0.0f);
        float v2 = s[nt][2] * scale + ((rg0 != mreg_hi) ? -1e9f : 0.0f);
        float v3 = s[nt][3] * scale + ((rg1 != mreg_hi) ? -1e9f : 0.0f);
        s[nt][0] = v0; s[nt][1] = v1; s[nt][2] = v2; s[nt][3] = v3;
        mx_lo = fmaxf(mx_lo, fmaxf(v0, v1));
        mx_hi = fmaxf(mx_hi, fmaxf(v2, v3));
    }
    #pragma unroll
    for (int off = 1; off <= 2; off <<= 1) {
        mx_lo = fmaxf(mx_lo, __shfl_xor_sync(0xffffffffu, mx_lo, off));
        mx_hi = fmaxf(mx_hi, __shfl_xor_sync(0xffffffffu, mx_hi, off));
    }
    float sum_lo = 0.0f, sum_hi = 0.0f;
    #pragma unroll
    for (int nt = 0; nt < 8; ++nt) {
        float e0 = __expf(s[nt][0] - mx_lo);
        float e1 = __expf(s[nt][1] - mx_lo);
        float e2 = __expf(s[nt][2] - mx_hi);
        float e3 = __expf(s[nt][3] - mx_hi);
        s[nt][0] = e0; s[nt][1] = e1; s[nt][2] = e2; s[nt][3] = e3;
        sum_lo += e0 + e1; sum_hi += e2 + e3;
    }
    #pragma unroll
    for (int off = 1; off <= 2; off <<= 1) {
        sum_lo += __shfl_xor_sync(0xffffffffu, sum_lo, off);
        sum_hi += __shfl_xor_sync(0xffffffffu, sum_hi, off);
    }
    float inv_lo = 1.0f / sum_lo, inv_hi = 1.0f / sum_hi;
    #pragma unroll
    for (int nt = 0; nt < 8; ++nt) {
        s[nt][0] *= inv_lo; s[nt][1] *= inv_lo;
        s[nt][2] *= inv_hi; s[nt][3] *= inv_hi;
    }

    // ---- O = P V : P converts in-register to A-operand frags ----
    float ov[4][4];
    #pragma unroll
    for (int nt = 0; nt < 4; ++nt)
        #pragma unroll
        for (int r = 0; r < 4; ++r) ov[nt][r] = 0.0f;

    #pragma unroll
    for (int kt2 = 0; kt2 < 4; ++kt2) {
        uint32_t a[4];
        a[0] = f2bf2(s[2 * kt2][0],     s[2 * kt2][1]);
        a[1] = f2bf2(s[2 * kt2][2],     s[2 * kt2][3]);
        a[2] = f2bf2(s[2 * kt2 + 1][0], s[2 * kt2 + 1][1]);
        a[3] = f2bf2(s[2 * kt2 + 1][2], s[2 * kt2 + 1][3]);
        uint32_t bt0[4], bt1[4];
        ldmx4t(bt0, sV + ((kt2 * 16 + lrow) * 104 + head * 32 + lk8) * 2);
        ldmx4t(bt1, sV + ((kt2 * 16 + lrow) * 104 + head * 32 + 16 + lk8) * 2);
        mma_bf16(ov[0], a, bt0[0], bt0[1]);
        mma_bf16(ov[1], a, bt0[2], bt0[3]);
        mma_bf16(ov[2], a, bt1[0], bt1[1]);
        mma_bf16(ov[3], a, bt1[2], bt1[3]);
    }

    // ---- store O (bf16 [T,128]) ----
    #pragma unroll
    for (int nt = 0; nt < 4; ++nt) {
        int col = head * 32 + nt * 8 + c0;
        if (r_lo < 49)
            *(uint32_t*)(o + (size_t)tokS[r_lo] * 128 + col) = f2bf2(ov[nt][0], ov[nt][1]);
        if (r_hi < 49)
            *(uint32_t*)(o + (size_t)tokS[r_hi] * 128 + col) = f2bf2(ov[nt][2], ov[nt][3]);
    }
    // zero pad cols 96..127
    for (int u = tid; u < 49 * 16; u += 384) {
        int r = u >> 4, cg = u & 15;
        *(uint32_t*)(o + (size_t)tokS[r] * 128 + 96 + cg * 2) = 0u;
    }
}

// ---------------------------------------------------------------------------
// Launch
// ---------------------------------------------------------------------------
extern "C" void kernel_launch(void* const* d_in, const int* in_sizes, int n_in,
                              void* d_out, int out_size)
{
    const float* x     = (const float*)d_in[0];
    const float* qkv_w = (const float*)d_in[1];
    const float* qkv_b = (const float*)d_in[2];
    const float* out_w = (const float*)d_in[3];
    const float* out_b = (const float*)d_in[4];
    const float* ln1_w = (const float*)d_in[5];
    const float* ln1_b = (const float*)d_in[6];
    const float* ln2_w = (const float*)d_in[7];
    const float* ln2_b = (const float*)d_in[8];
    const float* ff1_w = (const float*)d_in[9];
    const float* ff1_b = (const float*)d_in[10];
    const float* ff2_w = (const float*)d_in[11];
    const float* ff2_b = (const float*)d_in[12];
    float* out = (float*)d_out;

    __nv_bfloat16 *p_h, *p_qkv, *p_ff;
    float *p_x1;
    cudaGetSymbolAddress((void**)&p_h,   g_h);
    cudaGetSymbolAddress((void**)&p_qkv, g_qkv);
    cudaGetSymbolAddress((void**)&p_x1,  g_x1);
    cudaGetSymbolAddress((void**)&p_ff,  g_ff);

    const int MB = T_TOK / 128;   // 3136 row tiles

    // 1. h = LN1(x)                                   (bf16 [T,128])
    ln_kernel<<<T_TOK / 4, 128>>>(x, ln1_w, ln1_b, p_h);
    // 2. qkv = h @ qkv_w^T + qkv_b                    (bf16 [T,288])
    gemm_hmma<288, 96, 2, 0><<<dim3(3, MB), 256>>>(p_h, qkv_w, qkv_b, nullptr, p_qkv,
                                                   nullptr, nullptr, nullptr);
    // 3. o = windowed masked attention (tensor core)  (bf16 [T,128], into g_h)
    attn_mma<<<8192, 384>>>(p_qkv, p_h);
    // 4. x1 = x + o @ out_w^T + out_b ; h2 = LN2(x1)  (fp32 [T,96] + bf16 [T,128])
    gemm_hmma<96, 96, 2, 3><<<dim3(1, MB), 256>>>(p_h, out_w, out_b, x, p_x1,
                                                  ln2_w, ln2_b, p_qkv);
    // 5. ff = gelu(h2 @ ff1_w^T + ff1_b)              (bf16 [T,384])
    gemm_hmma<384, 96, 2, 2><<<dim3(4, MB), 256>>>(p_qkv, ff1_w, ff1_b, nullptr, p_ff,
                                                   nullptr, nullptr, nullptr);
    // 6. out = x1 + ff @ ff2_w^T + ff2_b              (fp32 [T,96])
    gemm_hmma<96, 384, 6, 1><<<dim3(1, MB), 256>>>(p_ff, ff2_w, ff2_b, p_x1, out,
                                                   nullptr, nullptr, nullptr);
}